// round 16
// baseline (speedup 1.0000x reference)
#include <cuda_runtime.h>
#include <cuda_bf16.h>
#include <cuda_fp16.h>
#include <math_constants.h>
#include <cstdint>

#define NS 100000
#define ND 100000
#define NE 1600000
#define DIN 256
#define NH 4
#define DH 32
#define HD 128          // NH * DH
#define NEG_SLOPE 0.2f
#define NBLK ((ND + 255) / 256)   // 391 scan blocks
#define NSP 100096                // NS padded to 128 (782 CTAs * 128)
#define CONVA_BLOCKS ((NS * (DIN / 4) + 255) / 256)   // 25000
#define HIST_BLOCKS  (NE / 256)                        // 6250

// ---------------- scratch (device globals; no allocs allowed) ----------------
__device__ __align__(16) __half g_fsh[(size_t)NS * HD];  // 25.6 MB fp16 projected feats
__device__ __align__(16) __nv_bfloat16 g_ahi[(size_t)NSP * DIN];  // A split hi
__device__ __align__(16) __nv_bfloat16 g_alo[(size_t)NSP * DIN];  // A split lo
__device__ __align__(16) __nv_bfloat16 g_bhi[HD * DIN];  // w_src hi, n-major [128][256]
__device__ __align__(16) __nv_bfloat16 g_blo[HD * DIN];  // w_src lo, n-major
__device__ __align__(16) float g_esrc[NS * NH];
__device__ __align__(16) float g_edst[ND * NH];
__device__ __align__(16) float g_vdst[DIN * NH];         // folded w_dst @ attn_dst
__device__ int  g_cnt[ND];
__device__ int  g_wpos[ND];
__device__ int  g_base[ND];
__device__ int  g_bsum[NBLK];
__device__ int  g_boff[NBLK];
__device__ int  g_ssrc[NE];       // src id per dst-sorted slot

// ---------------- K0: init counters ----------------
__global__ void init_kernel() {
    int tix = blockIdx.x * blockDim.x + threadIdx.x;
    if (tix < ND) { g_cnt[tix] = 0; g_wpos[tix] = 0; }
}

// ---------------- P1: split A -> bf16 hi/lo, fused with dst histogram -------
__global__ __launch_bounds__(256) void convA_hist_kernel(
    const float* __restrict__ A, const int* __restrict__ dst)
{
    if (blockIdx.x < CONVA_BLOCKS) {
        size_t i = (size_t)blockIdx.x * blockDim.x + threadIdx.x;
        if (i >= (size_t)NS * (DIN / 4)) return;
        float4 v = ((const float4*)A)[i];
        __nv_bfloat162 h0 = __floats2bfloat162_rn(v.x, v.y);
        __nv_bfloat162 h1 = __floats2bfloat162_rn(v.z, v.w);
        float2 f0 = __bfloat1622float2(h0);
        float2 f1 = __bfloat1622float2(h1);
        __nv_bfloat162 l0 = __floats2bfloat162_rn(v.x - f0.x, v.y - f0.y);
        __nv_bfloat162 l1 = __floats2bfloat162_rn(v.z - f1.x, v.w - f1.y);
        ((uint2*)g_ahi)[i] = make_uint2(*(uint32_t*)&h0, *(uint32_t*)&h1);
        ((uint2*)g_alo)[i] = make_uint2(*(uint32_t*)&l0, *(uint32_t*)&l1);
    } else {
        int i = (blockIdx.x - CONVA_BLOCKS) * blockDim.x + threadIdx.x;
        if (i < NE) atomicAdd(&g_cnt[dst[i]], 1);
    }
}

// ---------------- P2: split B -> bf16 hi/lo, transposed to n-major ----------
__global__ void convB_kernel(const float* __restrict__ B)
{
    int i = blockIdx.x * blockDim.x + threadIdx.x;
    if (i >= DIN * HD) return;
    int k = i >> 7, n = i & 127;
    float v = B[i];
    __nv_bfloat16 h = __float2bfloat16(v);
    __nv_bfloat16 l = __float2bfloat16(v - __bfloat162float(h));
    g_bhi[n * DIN + k] = h;
    g_blo[n * DIN + k] = l;
}

// ---------------- K1: fs = A @ B via mma.sync bf16x3 + ldmatrix -------------
#define KCH 16
#define SSTR 24      // bf16 stride (48 B): LDSM rows hit banks 12r%32, distinct
#define NCH (DIN / KCH)
#define ARR_STRIDE (128 * SSTR * 2)       // 6144 B
#define STAGE_STRIDE (4 * ARR_STRIDE)     // 24576 B

__device__ __forceinline__ void mma16816(float* c, const uint32_t* a, const uint32_t* b) {
    asm volatile("mma.sync.aligned.m16n8k16.row.col.f32.bf16.bf16.f32 "
                 "{%0,%1,%2,%3}, {%4,%5,%6,%7}, {%8,%9}, {%0,%1,%2,%3};"
                 : "+f"(c[0]), "+f"(c[1]), "+f"(c[2]), "+f"(c[3])
                 : "r"(a[0]), "r"(a[1]), "r"(a[2]), "r"(a[3]), "r"(b[0]), "r"(b[1]));
}
__device__ __forceinline__ void ldsm_x4(uint32_t* r, uint32_t addr) {
    asm volatile("ldmatrix.sync.aligned.m8n8.x4.shared.b16 {%0,%1,%2,%3}, [%4];"
                 : "=r"(r[0]), "=r"(r[1]), "=r"(r[2]), "=r"(r[3]) : "r"(addr));
}
__device__ __forceinline__ uint32_t smem_u32(const void* p) {
    uint32_t a;
    asm("{ .reg .u64 t; cvta.to.shared.u64 t, %1; cvt.u32.u64 %0, t; }" : "=r"(a) : "l"(p));
    return a;
}
__device__ __forceinline__ void cpa16(uint32_t dst, const void* src) {
    asm volatile("cp.async.cg.shared.global [%0], [%1], 16;" :: "r"(dst), "l"(src));
}
#define CP_COMMIT() asm volatile("cp.async.commit_group;" ::: "memory")
#define CP_WAIT0()  asm volatile("cp.async.wait_group 0;" ::: "memory")

__global__ __launch_bounds__(256, 2) void gemm_mma_kernel()
{
    __shared__ __align__(16) __nv_bfloat16 S[2][4][128][SSTR];   // 49152 B

    const int tid  = threadIdx.x;
    const int wid  = tid >> 5;
    const int lane = tid & 31;
    const int grp  = lane >> 2;
    const int quad = lane & 3;
    const int mwarp = (wid & 3) * 32;
    const int nwarp = (wid >> 2) * 64;
    const int row0  = blockIdx.x * 128;

    const uint32_t Sbase = smem_u32(&S[0][0][0][0]);

    const uint32_t aoff0 = (uint32_t)((mwarp + ((lane >> 3) & 1) * 8 + (lane & 7)) * (SSTR * 2)
                                      + (lane >> 4) * 16);
    const uint32_t aoff1 = aoff0 + 16 * (SSTR * 2);
    uint32_t boff[4];
#pragma unroll
    for (int p = 0; p < 4; p++)
        boff[p] = (uint32_t)((nwarp + 16 * p + (lane >> 4) * 8 + (lane & 7)) * (SSTR * 2)
                             + ((lane >> 3) & 1) * 16);

    float acc[2][8][4];
#pragma unroll
    for (int mf = 0; mf < 2; mf++)
#pragma unroll
        for (int nf = 0; nf < 8; nf++)
#pragma unroll
            for (int q = 0; q < 4; q++) acc[mf][nf][q] = 0.0f;

    auto copy_chunk = [&](int ch, int stage) {
        const int k0 = ch * KCH;
#pragma unroll
        for (int i = 0; i < 4; i++) {
            int idx = i * 256 + tid;
            int arr = idx >> 8;
            int row = (idx >> 1) & 127;
            int seg = idx & 1;
            const __nv_bfloat16* sp;
            if (arr == 0)      sp = g_ahi + (size_t)(row0 + row) * DIN + k0 + seg * 8;
            else if (arr == 1) sp = g_alo + (size_t)(row0 + row) * DIN + k0 + seg * 8;
            else if (arr == 2) sp = g_bhi + (size_t)row * DIN + k0 + seg * 8;
            else               sp = g_blo + (size_t)row * DIN + k0 + seg * 8;
            cpa16(smem_u32(&S[stage][arr][row][seg * 8]), sp);
        }
    };

    copy_chunk(0, 0);
    CP_COMMIT();
    CP_WAIT0();
    __syncthreads();

    int buf = 0;
    for (int ch = 0; ch < NCH; ch++) {
        if (ch + 1 < NCH) {
            copy_chunk(ch + 1, buf ^ 1);
            CP_COMMIT();
        }

        const uint32_t sb = Sbase + (uint32_t)buf * STAGE_STRIDE;
        uint32_t ah[2][4], al[2][4], bh[8][2], bl[8][2];
        ldsm_x4(ah[0], sb + 0 * ARR_STRIDE + aoff0);
        ldsm_x4(ah[1], sb + 0 * ARR_STRIDE + aoff1);
        ldsm_x4(al[0], sb + 1 * ARR_STRIDE + aoff0);
        ldsm_x4(al[1], sb + 1 * ARR_STRIDE + aoff1);
#pragma unroll
        for (int p = 0; p < 4; p++) {
            uint32_t t[4];
            ldsm_x4(t, sb + 2 * ARR_STRIDE + boff[p]);
            bh[2 * p][0] = t[0]; bh[2 * p][1] = t[1];
            bh[2 * p + 1][0] = t[2]; bh[2 * p + 1][1] = t[3];
            ldsm_x4(t, sb + 3 * ARR_STRIDE + boff[p]);
            bl[2 * p][0] = t[0]; bl[2 * p][1] = t[1];
            bl[2 * p + 1][0] = t[2]; bl[2 * p + 1][1] = t[3];
        }

#pragma unroll
        for (int mf = 0; mf < 2; mf++)
#pragma unroll
            for (int nf = 0; nf < 8; nf++) {
                mma16816(acc[mf][nf], ah[mf], bh[nf]);
                mma16816(acc[mf][nf], al[mf], bh[nf]);
                mma16816(acc[mf][nf], ah[mf], bl[nf]);
            }

        if (ch + 1 < NCH) CP_WAIT0();
        __syncthreads();
        buf ^= 1;
    }

    // ---- writeback (fp16) ----
#pragma unroll
    for (int mf = 0; mf < 2; mf++) {
        const int r0w = row0 + mwarp + mf * 16 + grp;
        const int r1w = r0w + 8;
#pragma unroll
        for (int nf = 0; nf < 8; nf++) {
            const int col = nwarp + nf * 8 + quad * 2;
            if (r0w < NS)
                *(__half2*)(g_fsh + (size_t)r0w * HD + col) =
                    __floats2half2_rn(acc[mf][nf][0], acc[mf][nf][1]);
            if (r1w < NS)
                *(__half2*)(g_fsh + (size_t)r1w * HD + col) =
                    __floats2half2_rn(acc[mf][nf][2], acc[mf][nf][3]);
        }
    }
}

// ---------------- K2a: fold v_dst[k][h] = sum_j w_dst[k,h*32+j]*attn[h,j] ---
__global__ void vdst_kernel(const float* __restrict__ wd,
                            const float* __restrict__ attn)
{
    int t = blockIdx.x * blockDim.x + threadIdx.x;
    if (t >= DIN * NH) return;
    int k = t >> 2, h = t & 3;
    float s = 0.0f;
#pragma unroll
    for (int j = 0; j < DH; j++)
        s += wd[(size_t)k * HD + h * DH + j] * attn[h * (2 * DH) + j];
    g_vdst[k * NH + h] = s;
}

// ---------------- K2b: e_dst, float4 global loads + padded smem -------------
__global__ __launch_bounds__(256) void edst_kernel(const float* __restrict__ fd)
{
    __shared__ float vsd[NH][DIN + 8];
    int tid = threadIdx.x;
    for (int i = tid; i < DIN * NH; i += 256) {
        int k = i >> 2, h = i & 3;
        vsd[h][k + (k >> 5)] = g_vdst[i];
    }
    __syncthreads();
    int warp = tid >> 5, lane = tid & 31;
    int n = blockIdx.x * 8 + warp;
    if (n >= ND) return;
    const float4* fr4 = (const float4*)(fd + (size_t)n * DIN);
    float4 x = fr4[lane];
    float4 y = fr4[lane + 32];
    float fx[8] = {x.x, x.y, x.z, x.w, y.x, y.y, y.z, y.w};
    float a0 = 0, a1 = 0, a2 = 0, a3 = 0;
#pragma unroll
    for (int j = 0; j < 8; j++) {
        int k = (j < 4) ? (4 * lane + j) : (128 + 4 * lane + (j - 4));
        int idx = k + (k >> 5);
        a0 += fx[j] * vsd[0][idx];
        a1 += fx[j] * vsd[1][idx];
        a2 += fx[j] * vsd[2][idx];
        a3 += fx[j] * vsd[3][idx];
    }
#pragma unroll
    for (int o = 16; o >= 1; o >>= 1) {
        a0 += __shfl_down_sync(0xffffffffu, a0, o);
        a1 += __shfl_down_sync(0xffffffffu, a1, o);
        a2 += __shfl_down_sync(0xffffffffu, a2, o);
        a3 += __shfl_down_sync(0xffffffffu, a3, o);
    }
    if (lane == 0) {
        g_edst[n * NH + 0] = a0;
        g_edst[n * NH + 1] = a1;
        g_edst[n * NH + 2] = a2;
        g_edst[n * NH + 3] = a3;
    }
}

// ---------------- K2c: e_src from fp16 fs (warp per node) -------------------
__global__ __launch_bounds__(256) void esrc_kernel(const float* __restrict__ attn)
{
    int tid = threadIdx.x;
    int warp = tid >> 5, lane = tid & 31;
    int n = blockIdx.x * 8 + warp;
    if (n >= NS) return;
    int h = lane >> 3;
    int j = (lane & 7) * 4;
    uint2 u = *(const uint2*)&g_fsh[(size_t)n * HD + lane * 4];
    float2 f0 = __half22float2(*(__half2*)&u.x);
    float2 f1 = __half22float2(*(__half2*)&u.y);
    const float* ar = attn + h * (2 * DH) + DH + j;
    float p = f0.x * ar[0] + f0.y * ar[1] + f1.x * ar[2] + f1.y * ar[3];
    p += __shfl_down_sync(0xffffffffu, p, 4, 8);
    p += __shfl_down_sync(0xffffffffu, p, 2, 8);
    p += __shfl_down_sync(0xffffffffu, p, 1, 8);
    if ((lane & 7) == 0) g_esrc[n * NH + h] = p;
}

// ---------------- K4a: per-block exclusive scan of g_cnt --------------------
__global__ __launch_bounds__(256) void scan_block_kernel()
{
    int t = threadIdx.x;
    int i = blockIdx.x * 256 + t;
    int c = (i < ND) ? g_cnt[i] : 0;
    int lane = t & 31, w = t >> 5;
    int inc = c;
#pragma unroll
    for (int o = 1; o < 32; o <<= 1) {
        int n = __shfl_up_sync(0xffffffffu, inc, o);
        if (lane >= o) inc += n;
    }
    __shared__ int ws[8];
    if (lane == 31) ws[w] = inc;
    __syncthreads();
    if (t < 8) {
        int v = ws[t];
        int inc2 = v;
#pragma unroll
        for (int o = 1; o < 8; o <<= 1) {
            int n = __shfl_up_sync(0x000000ffu, inc2, o);
            if (t >= o) inc2 += n;
        }
        ws[t] = inc2 - v;
    }
    __syncthreads();
    int excl = inc - c + ws[w];
    if (i < ND) g_base[i] = excl;
    if (t == 255) g_bsum[blockIdx.x] = excl + c;
}

// ---------------- K4b: scan the 391 block sums ------------------------------
__global__ __launch_bounds__(512) void scan_top_kernel()
{
    int t = threadIdx.x;
    int c = (t < NBLK) ? g_bsum[t] : 0;
    int lane = t & 31, w = t >> 5;
    int inc = c;
#pragma unroll
    for (int o = 1; o < 32; o <<= 1) {
        int n = __shfl_up_sync(0xffffffffu, inc, o);
        if (lane >= o) inc += n;
    }
    __shared__ int ws[16];
    if (lane == 31) ws[w] = inc;
    __syncthreads();
    if (t < 16) {
        int v = ws[t];
        int inc2 = v;
#pragma unroll
        for (int o = 1; o < 16; o <<= 1) {
            int n = __shfl_up_sync(0x0000ffffu, inc2, o);
            if (t >= o) inc2 += n;
        }
        ws[t] = inc2 - v;
    }
    __syncthreads();
    if (t < NBLK) g_boff[t] = inc - c + ws[w];
}

// ---------------- K5: scatter src ids into dst-sorted order -----------------
__global__ void scatter_kernel(const int* __restrict__ src,
                               const int* __restrict__ dst)
{
    int i = blockIdx.x * blockDim.x + threadIdx.x;
    if (i >= NE) return;
    int d = dst[i];
    int s = src[i];
    int pos = atomicAdd(&g_wpos[d], 1);
    g_ssrc[g_base[d] + g_boff[d >> 8] + pos] = s;
}

// ---------------- K6: two-phase aggregation (max prepass + indep accum) -----
__global__ __launch_bounds__(256) void aggregate_kernel(float* __restrict__ out)
{
    int warp = threadIdx.x >> 5, lane = threadIdx.x & 31;
    int d = blockIdx.x * 8 + warp;
    if (d >= ND) return;
    int base = g_base[d] + g_boff[d >> 8];
    int cnt  = g_cnt[d];
    int h = lane >> 3;
    int ol = lane & 7;                       // lane within head octet
    float ed = __ldg(&g_edst[(size_t)d * NH + h]);

    // ---- phase 1: segment max, 8 lanes per head scan edges in parallel ----
    float m = -CUDART_INF_F;
    for (int j = ol; j < cnt; j += 8) {
        int s = __ldg(&g_ssrc[base + j]);
        float e = __ldg(&g_esrc[(size_t)s * NH + h]) + ed;
        e = e > 0.f ? e : NEG_SLOPE * e;
        m = fmaxf(m, e);
    }
    m = fmaxf(m, __shfl_xor_sync(0xffffffffu, m, 1));
    m = fmaxf(m, __shfl_xor_sync(0xffffffffu, m, 2));
    m = fmaxf(m, __shfl_xor_sync(0xffffffffu, m, 4));

    // ---- phase 2: independent accumulation (depth-2 pipeline) ----
    float denom = 0.0f;
    float4 acc = make_float4(0.f, 0.f, 0.f, 0.f);
    float e0; uint2 fu0;
    if (cnt > 0) {
        int s = __ldg(&g_ssrc[base]);
        e0  = __ldg(&g_esrc[(size_t)s * NH + h]) + ed;
        fu0 = *(const uint2*)&g_fsh[(size_t)s * HD + lane * 4];
    }
    for (int j = 0; j < cnt; j++) {
        float e1; uint2 fu1;
        if (j + 1 < cnt) {
            int s = __ldg(&g_ssrc[base + j + 1]);
            e1  = __ldg(&g_esrc[(size_t)s * NH + h]) + ed;
            fu1 = *(const uint2*)&g_fsh[(size_t)s * HD + lane * 4];
        }
        float e = e0 > 0.f ? e0 : NEG_SLOPE * e0;
        float w = __expf(e - m);
        float2 f0 = __half22float2(*(__half2*)&fu0.x);
        float2 f1 = __half22float2(*(__half2*)&fu0.y);
        denom += w;
        acc.x += w * f0.x;
        acc.y += w * f0.y;
        acc.z += w * f1.x;
        acc.w += w * f1.y;
        e0 = e1; fu0 = fu1;
    }
    float inv = (cnt > 0) ? 1.0f / denom : 0.0f;
    float4 o;
    o.x = fmaxf(acc.x * inv, 0.f);
    o.y = fmaxf(acc.y * inv, 0.f);
    o.z = fmaxf(acc.z * inv, 0.f);
    o.w = fmaxf(acc.w * inv, 0.f);
    *(float4*)(out + (size_t)d * HD + lane * 4) = o;
}

// ---------------- launch -----------------------------------------------------
extern "C" void kernel_launch(void* const* d_in, const int* in_sizes, int n_in,
                              void* d_out, int out_size)
{
    const float* feat_src = (const float*)d_in[0];
    const float* feat_dst = (const float*)d_in[1];
    const float* w_src    = (const float*)d_in[2];
    const float* w_dst    = (const float*)d_in[3];
    const float* attn     = (const float*)d_in[4];
    const int*   src_idx  = (const int*)d_in[5];
    const int*   dst_idx  = (const int*)d_in[6];
    float* out = (float*)d_out;

    init_kernel<<<(ND + 255) / 256, 256>>>();
    convA_hist_kernel<<<CONVA_BLOCKS + HIST_BLOCKS, 256>>>(feat_src, dst_idx);
    convB_kernel<<<(DIN * HD + 255) / 256, 256>>>(w_src);
    gemm_mma_kernel<<<NSP / 128, 256>>>();
    vdst_kernel<<<(DIN * NH + 255) / 256, 256>>>(w_dst, attn);
    edst_kernel<<<(ND + 7) / 8, 256>>>(feat_dst);
    esrc_kernel<<<(NS + 7) / 8, 256>>>(attn);
    scan_block_kernel<<<NBLK, 256>>>();
    scan_top_kernel<<<1, 512>>>();
    scatter_kernel<<<NE / 256, 256>>>(src_idx, dst_idx);
    aggregate_kernel<<<(ND + 7) / 8, 256>>>(out);
}